// round 10
// baseline (speedup 1.0000x reference)
#include <cuda_runtime.h>
#include <cuda_fp16.h>
#include <cuda_bf16.h>
#include <math.h>

#define NN 100000
#define EE 1600000
#define NEG_SLOPE 0.2f
#define SCAN_B 512
#define NBLK ((NN + SCAN_B - 1) / SCAN_B)   // 196
#define GEMM_BLOCKS ((NN + 255) / 256)       // 391
#define HIST_BLOCKS ((EE / 4 + 255) / 256)   // 1563

// ---------------- scratch (device globals) ----------------
__device__ __half2 g_h1h[NN * 32];  // layer1 GEMM output, fp16 packed
__device__ __half  g_as1h[NN * 8];  // per-node/head src logit (fp16)
__device__ float   g_ad1[NN * 8];   // per-node/head dst logit (fp32)
__device__ float   g_out1[NN * 64]; // layer1 final (ELU'd), fp32
__device__ __half  g_g2h[NN * 16];  // layer2 GEMM output (fp16)
__device__ float   g_as2[NN];
__device__ float   g_ad2[NN];
__device__ int     g_deg[NN];       // zero at load; self-reset by s3 each call
__device__ int     g_off[NN + 1];   // CSR offsets, sentinel off[NN]=EE
__device__ int     g_rank[EE];      // per-edge rank within its dst segment
__device__ int     g_csr[EE];       // src node ids, grouped by dst
__device__ int     g_bsum[NBLK];

// ---------------- KA: fused GEMM1 (+logits) and degree histogram (+ranks) ----------------
__global__ void __launch_bounds__(256) kA_gemm1_hist(
    const float* __restrict__ x, const float* __restrict__ W1,
    const float* __restrict__ a1s, const float* __restrict__ a1d,
    const int* __restrict__ dst)
{
    if (blockIdx.x >= GEMM_BLOCKS) {
        // ---- histogram part: 4 edges/thread, record ranks ----
        int t = (blockIdx.x - GEMM_BLOCKS) * 256 + threadIdx.x;
        if (t >= EE / 4) return;
        int4 d4 = ((const int4*)dst)[t];
        int r0 = atomicAdd(&g_deg[d4.x], 1);
        int r1 = atomicAdd(&g_deg[d4.y], 1);
        int r2 = atomicAdd(&g_deg[d4.z], 1);
        int r3 = atomicAdd(&g_deg[d4.w], 1);
        ((int4*)g_rank)[t] = make_int4(r0, r1, r2, r3);
        return;
    }

    // ---- GEMM part ----
    __shared__ float sW[128 * 64];
    __shared__ float sA[128];
    for (int i = threadIdx.x; i < 128 * 64; i += blockDim.x) sW[i] = W1[i];
    for (int i = threadIdx.x; i < 128; i += blockDim.x)
        sA[i] = (i < 64) ? a1s[i] : a1d[i - 64];
    __syncthreads();

    int row = blockIdx.x * blockDim.x + threadIdx.x;
    if (row >= NN) return;

    float acc[64];
#pragma unroll
    for (int j = 0; j < 64; j++) acc[j] = 0.0f;

    const float4* x4 = (const float4*)(x + (size_t)row * 128);
#pragma unroll 1
    for (int kc = 0; kc < 32; kc++) {
        float4 xv = __ldg(x4 + kc);
#pragma unroll
        for (int t = 0; t < 4; t++) {
            float xs = (t == 0) ? xv.x : (t == 1) ? xv.y : (t == 2) ? xv.z : xv.w;
            const float4* wrow = (const float4*)(sW + (kc * 4 + t) * 64);
#pragma unroll
            for (int j4 = 0; j4 < 16; j4++) {
                float4 w = wrow[j4];
                acc[j4 * 4 + 0] += xs * w.x;
                acc[j4 * 4 + 1] += xs * w.y;
                acc[j4 * 4 + 2] += xs * w.z;
                acc[j4 * 4 + 3] += xs * w.w;
            }
        }
    }

    __half2* h1o = g_h1h + (size_t)row * 32;
#pragma unroll
    for (int j = 0; j < 32; j++)
        h1o[j] = __floats2half2_rn(acc[j * 2], acc[j * 2 + 1]);

#pragma unroll
    for (int h = 0; h < 8; h++) {
        float s = 0.0f, d = 0.0f;
#pragma unroll
        for (int q = 0; q < 8; q++) {
            s += acc[h * 8 + q] * sA[h * 8 + q];
            d += acc[h * 8 + q] * sA[64 + h * 8 + q];
        }
        g_as1h[row * 8 + h] = __float2half(s);
        g_ad1[row * 8 + h] = d;
    }
}

// ---------------- scans ----------------
__global__ void s1_scan() {
    __shared__ int sd[SCAN_B];
    int i = blockIdx.x * SCAN_B + threadIdx.x;
    int v = (i < NN) ? g_deg[i] : 0;
    sd[threadIdx.x] = v;
    __syncthreads();
    for (int ofs = 1; ofs < SCAN_B; ofs <<= 1) {
        int t = (threadIdx.x >= ofs) ? sd[threadIdx.x - ofs] : 0;
        __syncthreads();
        sd[threadIdx.x] += t;
        __syncthreads();
    }
    if (i < NN) g_off[i] = sd[threadIdx.x] - v;           // exclusive within block
    if (threadIdx.x == SCAN_B - 1) g_bsum[blockIdx.x] = sd[threadIdx.x];
}

// cross-block scan + apply + sentinel + deg self-reset
__global__ void s3_apply() {
    __shared__ int sbase;
    int b = blockIdx.x;
    if (threadIdx.x < 32) {
        int p = 0;
        for (int i = threadIdx.x; i < b; i += 32) p += g_bsum[i];
#pragma unroll
        for (int o = 16; o; o >>= 1) p += __shfl_xor_sync(0xFFFFFFFFu, p, o);
        if (threadIdx.x == 0) sbase = p;
    }
    __syncthreads();
    int i = b * SCAN_B + threadIdx.x;
    if (i < NN) {
        int o = g_off[i] + sbase;
        g_off[i] = o;
        if (i == NN - 1) g_off[NN] = o + g_deg[i];   // sentinel
        g_deg[i] = 0;                                 // ready for next replay
    }
}

// ---------------- scatter: atomic-free (uses precomputed ranks) ----------------
__global__ void k_scatter(const int* __restrict__ src, const int* __restrict__ dst) {
    int t = blockIdx.x * blockDim.x + threadIdx.x;   // over EE/4
    if (t >= EE / 4) return;
    int4 s4 = ((const int4*)src)[t];
    int4 d4 = ((const int4*)dst)[t];
    int4 r4 = ((const int4*)g_rank)[t];
    g_csr[g_off[d4.x] + r4.x] = s4.x;
    g_csr[g_off[d4.y] + r4.y] = s4.y;
    g_csr[g_off[d4.z] + r4.z] = s4.z;
    g_csr[g_off[d4.w] + r4.w] = s4.w;
}

// ---------------- G1: warp-per-dst gather, 4-edge batched logits, fp16 feeds ----------------
__global__ void __launch_bounds__(256) g1_gather(const float* __restrict__ b1) {
    int warp = (blockIdx.x * 256 + threadIdx.x) >> 5;
    int lane = threadIdx.x & 31;
    if (warp >= NN) return;
    int n = warp;
    int off = g_off[n];
    int deg = g_off[n + 1] - off;
    int h8 = lane & 7;            // head index in logit phase (lane = edge*8 + h8)
    int h4 = lane >> 2;           // head owning this lane's 2 dims
    float adf = g_ad1[n * 8 + h8];

    float2 acc = make_float2(0.0f, 0.0f);
    float den = 0.0f;

    for (int base = 0; base < deg; base += 32) {
        int idx = base + lane;
        int sreg = (idx < deg) ? g_csr[off + idx] : 0;
        int cnt = min(32, deg - base);
        for (int g = 0; g < cnt; g += 4) {
            int le = g + (lane >> 3);
            int sl = __shfl_sync(0xFFFFFFFFu, sreg, le);
            float e = __half2float(g_as1h[sl * 8 + h8]) + adf;
            e = (e >= 0.0f) ? e : NEG_SLOPE * e;
            float p = __expf(e);
            if (base + le >= deg) p = 0.0f;
#pragma unroll
            for (int j = 0; j < 4; j++) {
                int s = __shfl_sync(0xFFFFFFFFu, sreg, g + j);
                float pj = __shfl_sync(0xFFFFFFFFu, p, j * 8 + h4);
                float2 v = __half22float2(g_h1h[(size_t)s * 32 + lane]);
                acc.x += pj * v.x;
                acc.y += pj * v.y;
                den += pj;
            }
        }
    }

    float inv = (den > 0.0f) ? (1.0f / den) : 0.0f;
    float r0 = acc.x * inv + b1[2 * lane];
    float r1 = acc.y * inv + b1[2 * lane + 1];
    r0 = (r0 > 0.0f) ? r0 : (__expf(r0) - 1.0f);
    r1 = (r1 > 0.0f) ? r1 : (__expf(r1) - 1.0f);
    *(float2*)(g_out1 + (size_t)n * 64 + 2 * lane) = make_float2(r0, r1);
}

// ---------------- K5: g2 = elu_h @ W2 (+ layer2 attention logits) ----------------
__global__ void __launch_bounds__(256) k5_gemm2(
    const float* __restrict__ W2, const float* __restrict__ a2s,
    const float* __restrict__ a2d)
{
    __shared__ float sW[64 * 16];
    __shared__ float sA[32];
    for (int i = threadIdx.x; i < 64 * 16; i += blockDim.x) sW[i] = W2[i];
    for (int i = threadIdx.x; i < 32; i += blockDim.x)
        sA[i] = (i < 16) ? a2s[i] : a2d[i - 16];
    __syncthreads();

    int row = blockIdx.x * blockDim.x + threadIdx.x;
    if (row >= NN) return;

    float acc[16];
#pragma unroll
    for (int j = 0; j < 16; j++) acc[j] = 0.0f;

    const float4* x4 = (const float4*)(g_out1 + (size_t)row * 64);
#pragma unroll 1
    for (int kc = 0; kc < 16; kc++) {
        float4 xv = x4[kc];
#pragma unroll
        for (int t = 0; t < 4; t++) {
            float xs = (t == 0) ? xv.x : (t == 1) ? xv.y : (t == 2) ? xv.z : xv.w;
            const float4* wrow = (const float4*)(sW + (kc * 4 + t) * 16);
#pragma unroll
            for (int j4 = 0; j4 < 4; j4++) {
                float4 w = wrow[j4];
                acc[j4 * 4 + 0] += xs * w.x;
                acc[j4 * 4 + 1] += xs * w.y;
                acc[j4 * 4 + 2] += xs * w.z;
                acc[j4 * 4 + 3] += xs * w.w;
            }
        }
    }

    __half* go = g_g2h + (size_t)row * 16;
#pragma unroll
    for (int j = 0; j < 16; j++) go[j] = __float2half(acc[j]);

    float s = 0.0f, d = 0.0f;
#pragma unroll
    for (int j = 0; j < 16; j++) { s += acc[j] * sA[j]; d += acc[j] * sA[16 + j]; }
    g_as2[row] = s;
    g_ad2[row] = d;
}

// ---------------- G2: warp-per-dst gather, 32-edge batched logits ----------------
__global__ void __launch_bounds__(256) g2_gather(const float* __restrict__ b2,
                                                 float* __restrict__ out) {
    int warp = (blockIdx.x * 256 + threadIdx.x) >> 5;
    int lane = threadIdx.x & 31;
    if (warp >= NN) return;
    int n = warp;
    int off = g_off[n];
    int deg = g_off[n + 1] - off;
    int half = lane >> 4;      // which of 2 edges per accumulation step
    int d16 = lane & 15;       // output class
    float ad = g_ad2[n];

    float acc = 0.0f, den = 0.0f;

    for (int base = 0; base < deg; base += 32) {
        int idx = base + lane;
        int sreg = (idx < deg) ? g_csr[off + idx] : 0;
        float e = g_as2[sreg] + ad;
        e = (e >= 0.0f) ? e : NEG_SLOPE * e;
        float p = __expf(e);
        if (idx >= deg) p = 0.0f;
        int cnt = min(32, deg - base);
        for (int g = 0; g < cnt; g += 2) {
            int s = __shfl_sync(0xFFFFFFFFu, sreg, g + half);
            float pj = __shfl_sync(0xFFFFFFFFu, p, g + half);
            float v = __half2float(g_g2h[(size_t)s * 16 + d16]);
            acc += pj * v;
            den += pj;
        }
    }

    acc += __shfl_xor_sync(0xFFFFFFFFu, acc, 16);
    den += __shfl_xor_sync(0xFFFFFFFFu, den, 16);

    float z = ((den > 0.0f) ? (acc / den) : 0.0f) + b2[d16];

    float m = z;
#pragma unroll
    for (int ofs = 1; ofs < 16; ofs <<= 1)
        m = fmaxf(m, __shfl_xor_sync(0xFFFFFFFFu, m, ofs));
    float sum = __expf(z - m);
#pragma unroll
    for (int ofs = 1; ofs < 16; ofs <<= 1)
        sum += __shfl_xor_sync(0xFFFFFFFFu, sum, ofs);
    float lse = m + logf(sum);

    if (lane < 16) out[(size_t)n * 16 + d16] = z - lse;
}

// ---------------- launcher ----------------
extern "C" void kernel_launch(void* const* d_in, const int* in_sizes, int n_in,
                              void* d_out, int out_size) {
    const float* x   = (const float*)d_in[0];
    const int*   ei  = (const int*)d_in[1];
    const float* W1  = (const float*)d_in[2];
    const float* a1s = (const float*)d_in[3];
    const float* a1d = (const float*)d_in[4];
    const float* b1  = (const float*)d_in[5];
    const float* W2  = (const float*)d_in[6];
    const float* a2s = (const float*)d_in[7];
    const float* a2d = (const float*)d_in[8];
    const float* b2  = (const float*)d_in[9];
    float* out = (float*)d_out;

    const int* src = ei;
    const int* dst = ei + EE;

    const int TB = 256;
    // fused GEMM1 + histogram (independent work, one launch)
    kA_gemm1_hist<<<GEMM_BLOCKS + HIST_BLOCKS, TB>>>(x, W1, a1s, a1d, dst);
    s1_scan<<<NBLK, SCAN_B>>>();
    s3_apply<<<NBLK, SCAN_B>>>();
    k_scatter<<<(EE / 4 + TB - 1) / TB, TB>>>(src, dst);   // atomic-free
    // layer 1 aggregation
    g1_gather<<<(NN * 32 + TB - 1) / TB, TB>>>(b1);
    // layer 2
    k5_gemm2<<<(NN + TB - 1) / TB, TB>>>(W2, a2s, a2d);
    g2_gather<<<(NN * 32 + TB - 1) / TB, TB>>>(b2, out);
}

// round 11
// speedup vs baseline: 1.0070x; 1.0070x over previous
#include <cuda_runtime.h>
#include <cuda_bf16.h>
#include <math.h>

#define NN 100000
#define EE 1600000
#define NEG_SLOPE 0.2f
#define SCAN_B 512
#define NBLK ((NN + SCAN_B - 1) / SCAN_B)   // 196
#define GEMM_BLOCKS ((NN + 255) / 256)       // 391
#define HIST_BLOCKS ((EE / 4 + 255) / 256)   // 1563
#define FULL 0xFFFFFFFFu

// ---------------- scratch (device globals) ----------------
__device__ float g_h1[NN * 64];     // layer1 GEMM output [N,H*D]
__device__ float g_as1[NN * 8];
__device__ float g_ad1[NN * 8];
__device__ float g_out1[NN * 64];   // layer1 final (ELU'd)
__device__ float g_g2[NN * 16];     // layer2 GEMM output
__device__ float g_as2[NN];
__device__ float g_ad2[NN];
__device__ int   g_deg[NN];         // zero at load; self-reset by s3 each call
__device__ int   g_off[NN + 1];     // CSR offsets, sentinel off[NN]=EE
__device__ int   g_rank[EE];        // per-edge rank within its dst segment
__device__ int   g_csr[EE];         // src node ids, grouped by dst
__device__ int   g_bsum[NBLK];

// ---------------- KA: fused GEMM1 (+logits) and degree histogram (+ranks) ----------------
__global__ void __launch_bounds__(256) kA_gemm1_hist(
    const float* __restrict__ x, const float* __restrict__ W1,
    const float* __restrict__ a1s, const float* __restrict__ a1d,
    const int* __restrict__ dst)
{
    if (blockIdx.x >= GEMM_BLOCKS) {
        int t = (blockIdx.x - GEMM_BLOCKS) * 256 + threadIdx.x;
        if (t >= EE / 4) return;
        int4 d4 = ((const int4*)dst)[t];
        int r0 = atomicAdd(&g_deg[d4.x], 1);
        int r1 = atomicAdd(&g_deg[d4.y], 1);
        int r2 = atomicAdd(&g_deg[d4.z], 1);
        int r3 = atomicAdd(&g_deg[d4.w], 1);
        ((int4*)g_rank)[t] = make_int4(r0, r1, r2, r3);
        return;
    }

    __shared__ float sW[128 * 64];
    __shared__ float sA[128];
    for (int i = threadIdx.x; i < 128 * 64; i += blockDim.x) sW[i] = W1[i];
    for (int i = threadIdx.x; i < 128; i += blockDim.x)
        sA[i] = (i < 64) ? a1s[i] : a1d[i - 64];
    __syncthreads();

    int row = blockIdx.x * blockDim.x + threadIdx.x;
    if (row >= NN) return;

    float acc[64];
#pragma unroll
    for (int j = 0; j < 64; j++) acc[j] = 0.0f;

    const float4* x4 = (const float4*)(x + (size_t)row * 128);
#pragma unroll 1
    for (int kc = 0; kc < 32; kc++) {
        float4 xv = __ldg(x4 + kc);
#pragma unroll
        for (int t = 0; t < 4; t++) {
            float xs = (t == 0) ? xv.x : (t == 1) ? xv.y : (t == 2) ? xv.z : xv.w;
            const float4* wrow = (const float4*)(sW + (kc * 4 + t) * 64);
#pragma unroll
            for (int j4 = 0; j4 < 16; j4++) {
                float4 w = wrow[j4];
                acc[j4 * 4 + 0] += xs * w.x;
                acc[j4 * 4 + 1] += xs * w.y;
                acc[j4 * 4 + 2] += xs * w.z;
                acc[j4 * 4 + 3] += xs * w.w;
            }
        }
    }

    float4* h1o = (float4*)(g_h1 + (size_t)row * 64);
#pragma unroll
    for (int j4 = 0; j4 < 16; j4++)
        h1o[j4] = make_float4(acc[j4 * 4], acc[j4 * 4 + 1], acc[j4 * 4 + 2], acc[j4 * 4 + 3]);

#pragma unroll
    for (int h = 0; h < 8; h++) {
        float s = 0.0f, d = 0.0f;
#pragma unroll
        for (int q = 0; q < 8; q++) {
            s += acc[h * 8 + q] * sA[h * 8 + q];
            d += acc[h * 8 + q] * sA[64 + h * 8 + q];
        }
        g_as1[row * 8 + h] = s;
        g_ad1[row * 8 + h] = d;
    }
}

// ---------------- scans ----------------
__global__ void s1_scan() {
    __shared__ int sd[SCAN_B];
    int i = blockIdx.x * SCAN_B + threadIdx.x;
    int v = (i < NN) ? g_deg[i] : 0;
    sd[threadIdx.x] = v;
    __syncthreads();
    for (int ofs = 1; ofs < SCAN_B; ofs <<= 1) {
        int t = (threadIdx.x >= ofs) ? sd[threadIdx.x - ofs] : 0;
        __syncthreads();
        sd[threadIdx.x] += t;
        __syncthreads();
    }
    if (i < NN) g_off[i] = sd[threadIdx.x] - v;
    if (threadIdx.x == SCAN_B - 1) g_bsum[blockIdx.x] = sd[threadIdx.x];
}

__global__ void s3_apply() {
    __shared__ int sbase;
    int b = blockIdx.x;
    if (threadIdx.x < 32) {
        int p = 0;
        for (int i = threadIdx.x; i < b; i += 32) p += g_bsum[i];
#pragma unroll
        for (int o = 16; o; o >>= 1) p += __shfl_xor_sync(FULL, p, o);
        if (threadIdx.x == 0) sbase = p;
    }
    __syncthreads();
    int i = b * SCAN_B + threadIdx.x;
    if (i < NN) {
        int o = g_off[i] + sbase;
        g_off[i] = o;
        if (i == NN - 1) g_off[NN] = o + g_deg[i];   // sentinel
        g_deg[i] = 0;                                 // ready for next replay
    }
}

// ---------------- scatter: atomic-free (uses precomputed ranks) ----------------
__global__ void k_scatter(const int* __restrict__ src, const int* __restrict__ dst) {
    int t = blockIdx.x * blockDim.x + threadIdx.x;
    if (t >= EE / 4) return;
    int4 s4 = ((const int4*)src)[t];
    int4 d4 = ((const int4*)dst)[t];
    int4 r4 = ((const int4*)g_rank)[t];
    g_csr[g_off[d4.x] + r4.x] = s4.x;
    g_csr[g_off[d4.y] + r4.y] = s4.y;
    g_csr[g_off[d4.z] + r4.z] = s4.z;
    g_csr[g_off[d4.w] + r4.w] = s4.w;
}

// ---------------- G1: warp-per-dst gather, pipelined (csr + logit prefetch) ----------------
__global__ void __launch_bounds__(256) g1_gather(const float* __restrict__ b1) {
    int warp = (blockIdx.x * 256 + threadIdx.x) >> 5;
    int lane = threadIdx.x & 31;
    if (warp >= NN) return;
    int n = warp;
    int off = g_off[n];
    int deg = g_off[n + 1] - off;
    int h8 = lane & 7;            // head index in logit phase
    int h4 = lane >> 2;           // head owning this lane's 2 dims
    float adf = g_ad1[n * 8 + h8];

    float2 acc = make_float2(0.0f, 0.0f);
    float den = 0.0f;

    // prefetch first window's csr
    int sreg = (lane < deg) ? g_csr[off + lane] : 0;

    for (int base = 0; base < deg; base += 32) {
        // prefetch next window's csr
        int sreg_n = 0;
        if (base + 32 < deg) {                       // warp-uniform
            int nl = base + 32 + lane;
            sreg_n = (nl < deg) ? g_csr[off + nl] : 0;
        }
        int cnt = min(32, deg - base);

        // prefetch first group's logit operand
        int sl0 = __shfl_sync(FULL, sreg, lane >> 3);
        float as = g_as1[sl0 * 8 + h8];

        for (int g = 0; g < cnt; g += 4) {
            // prefetch next group's logit operand
            float as_n = 0.0f;
            if (g + 4 < cnt) {                       // warp-uniform
                int sln = __shfl_sync(FULL, sreg, g + 4 + (lane >> 3));
                as_n = g_as1[sln * 8 + h8];
            }
            float e = as + adf;
            e = (e >= 0.0f) ? e : NEG_SLOPE * e;
            float p = __expf(e);
            if (base + g + (lane >> 3) >= deg) p = 0.0f;
#pragma unroll
            for (int j = 0; j < 4; j++) {
                int s = __shfl_sync(FULL, sreg, g + j);
                float pj = __shfl_sync(FULL, p, j * 8 + h4);
                float2 v = *(const float2*)(g_h1 + (size_t)s * 64 + 2 * lane);
                acc.x += pj * v.x;
                acc.y += pj * v.y;
                den += pj;
            }
            as = as_n;
        }
        sreg = sreg_n;
    }

    float inv = (den > 0.0f) ? (1.0f / den) : 0.0f;
    float r0 = acc.x * inv + b1[2 * lane];
    float r1 = acc.y * inv + b1[2 * lane + 1];
    r0 = (r0 > 0.0f) ? r0 : (__expf(r0) - 1.0f);
    r1 = (r1 > 0.0f) ? r1 : (__expf(r1) - 1.0f);
    *(float2*)(g_out1 + (size_t)n * 64 + 2 * lane) = make_float2(r0, r1);
}

// ---------------- K5: g2 = elu_h @ W2 (+ layer2 attention logits) ----------------
__global__ void __launch_bounds__(256) k5_gemm2(
    const float* __restrict__ W2, const float* __restrict__ a2s,
    const float* __restrict__ a2d)
{
    __shared__ float sW[64 * 16];
    __shared__ float sA[32];
    for (int i = threadIdx.x; i < 64 * 16; i += blockDim.x) sW[i] = W2[i];
    for (int i = threadIdx.x; i < 32; i += blockDim.x)
        sA[i] = (i < 16) ? a2s[i] : a2d[i - 16];
    __syncthreads();

    int row = blockIdx.x * blockDim.x + threadIdx.x;
    if (row >= NN) return;

    float acc[16];
#pragma unroll
    for (int j = 0; j < 16; j++) acc[j] = 0.0f;

    const float4* x4 = (const float4*)(g_out1 + (size_t)row * 64);
#pragma unroll 1
    for (int kc = 0; kc < 16; kc++) {
        float4 xv = x4[kc];
#pragma unroll
        for (int t = 0; t < 4; t++) {
            float xs = (t == 0) ? xv.x : (t == 1) ? xv.y : (t == 2) ? xv.z : xv.w;
            const float4* wrow = (const float4*)(sW + (kc * 4 + t) * 16);
#pragma unroll
            for (int j4 = 0; j4 < 4; j4++) {
                float4 w = wrow[j4];
                acc[j4 * 4 + 0] += xs * w.x;
                acc[j4 * 4 + 1] += xs * w.y;
                acc[j4 * 4 + 2] += xs * w.z;
                acc[j4 * 4 + 3] += xs * w.w;
            }
        }
    }

    float4* go = (float4*)(g_g2 + (size_t)row * 16);
#pragma unroll
    for (int j4 = 0; j4 < 4; j4++)
        go[j4] = make_float4(acc[j4 * 4], acc[j4 * 4 + 1], acc[j4 * 4 + 2], acc[j4 * 4 + 3]);

    float s = 0.0f, d = 0.0f;
#pragma unroll
    for (int j = 0; j < 16; j++) { s += acc[j] * sA[j]; d += acc[j] * sA[16 + j]; }
    g_as2[row] = s;
    g_ad2[row] = d;
}

// ---------------- G2: warp-per-dst gather, pipelined (csr + as2 prefetch) ----------------
__global__ void __launch_bounds__(256) g2_gather(const float* __restrict__ b2,
                                                 float* __restrict__ out) {
    int warp = (blockIdx.x * 256 + threadIdx.x) >> 5;
    int lane = threadIdx.x & 31;
    if (warp >= NN) return;
    int n = warp;
    int off = g_off[n];
    int deg = g_off[n + 1] - off;
    int half = lane >> 4;      // which of 2 edges per accumulation step
    int d16 = lane & 15;       // output class
    float ad = g_ad2[n];

    float acc = 0.0f, den = 0.0f;

    // prefetch first window
    int sreg = (lane < deg) ? g_csr[off + lane] : 0;
    float as = g_as2[sreg];

    for (int base = 0; base < deg; base += 32) {
        // prefetch next window
        int sreg_n = 0;
        float as_n = 0.0f;
        if (base + 32 < deg) {                       // warp-uniform
            int nl = base + 32 + lane;
            sreg_n = (nl < deg) ? g_csr[off + nl] : 0;
            as_n = g_as2[sreg_n];
        }

        float e = as + ad;
        e = (e >= 0.0f) ? e : NEG_SLOPE * e;
        float p = __expf(e);
        if (base + lane >= deg) p = 0.0f;
        int cnt = min(32, deg - base);
        for (int g = 0; g < cnt; g += 2) {
            int s = __shfl_sync(FULL, sreg, g + half);
            float pj = __shfl_sync(FULL, p, g + half);
            float v = g_g2[(size_t)s * 16 + d16];
            acc += pj * v;
            den += pj;
        }
        sreg = sreg_n;
        as = as_n;
    }

    acc += __shfl_xor_sync(FULL, acc, 16);
    den += __shfl_xor_sync(FULL, den, 16);

    float z = ((den > 0.0f) ? (acc / den) : 0.0f) + b2[d16];

    float m = z;
#pragma unroll
    for (int ofs = 1; ofs < 16; ofs <<= 1)
        m = fmaxf(m, __shfl_xor_sync(FULL, m, ofs));
    float sum = __expf(z - m);
#pragma unroll
    for (int ofs = 1; ofs < 16; ofs <<= 1)
        sum += __shfl_xor_sync(FULL, sum, ofs);
    float lse = m + logf(sum);

    if (lane < 16) out[(size_t)n * 16 + d16] = z - lse;
}

// ---------------- launcher ----------------
extern "C" void kernel_launch(void* const* d_in, const int* in_sizes, int n_in,
                              void* d_out, int out_size) {
    const float* x   = (const float*)d_in[0];
    const int*   ei  = (const int*)d_in[1];
    const float* W1  = (const float*)d_in[2];
    const float* a1s = (const float*)d_in[3];
    const float* a1d = (const float*)d_in[4];
    const float* b1  = (const float*)d_in[5];
    const float* W2  = (const float*)d_in[6];
    const float* a2s = (const float*)d_in[7];
    const float* a2d = (const float*)d_in[8];
    const float* b2  = (const float*)d_in[9];
    float* out = (float*)d_out;

    const int* src = ei;
    const int* dst = ei + EE;

    const int TB = 256;
    kA_gemm1_hist<<<GEMM_BLOCKS + HIST_BLOCKS, TB>>>(x, W1, a1s, a1d, dst);
    s1_scan<<<NBLK, SCAN_B>>>();
    s3_apply<<<NBLK, SCAN_B>>>();
    k_scatter<<<(EE / 4 + TB - 1) / TB, TB>>>(src, dst);
    g1_gather<<<(NN * 32 + TB - 1) / TB, TB>>>(b1);
    k5_gemm2<<<(NN + TB - 1) / TB, TB>>>(W2, a2s, a2d);
    g2_gather<<<(NN * 32 + TB - 1) / TB, TB>>>(b2, out);
}

// round 12
// speedup vs baseline: 1.3152x; 1.3059x over previous
#include <cuda_runtime.h>
#include <cuda_fp16.h>
#include <cuda_bf16.h>
#include <math.h>

#define NN 100000
#define EE 1600000
#define NEG_SLOPE 0.2f
#define SCAN_B 512
#define NBLK ((NN + SCAN_B - 1) / SCAN_B)      // 196
#define TC_BLOCKS ((NN + 127) / 128)            // 782 (tensor-core GEMM blocks)
#define HIST_BLOCKS ((EE / 4 + 255) / 256)      // 1563
#define FULL 0xFFFFFFFFu

// ---------------- scratch (device globals) ----------------
__device__ float g_h1[NN * 64];     // layer1 GEMM output [N,H*D]
__device__ float g_as1[NN * 8];
__device__ float g_ad1[NN * 8];
__device__ float g_out1[NN * 64];   // layer1 final (ELU'd)
__device__ float g_g2[NN * 16];     // layer2 GEMM output
__device__ float g_as2[NN];
__device__ float g_ad2[NN];
__device__ int   g_deg[NN];         // zero at load; self-reset by s3 each call
__device__ int   g_off[NN + 1];     // CSR offsets, sentinel off[NN]=EE
__device__ int   g_rank[EE];        // per-edge rank within its dst segment
__device__ int   g_csr[EE];         // src node ids, grouped by dst
__device__ int   g_bsum[NBLK];

__device__ __forceinline__ unsigned su32(const void* p) {
    return (unsigned)__cvta_generic_to_shared(p);
}

// ---------------- KA: tensor-core GEMM1 (+logits) fused with degree histogram ----------------
__global__ void __launch_bounds__(256) kA_gemm1_hist(
    const float* __restrict__ x, const float* __restrict__ W1,
    const float* __restrict__ a1s, const float* __restrict__ a1d,
    const int* __restrict__ dst)
{
    if (blockIdx.x >= TC_BLOCKS) {
        // ---- histogram part: 4 edges/thread, record ranks ----
        int t = (blockIdx.x - TC_BLOCKS) * 256 + threadIdx.x;
        if (t >= EE / 4) return;
        int4 d4 = ((const int4*)dst)[t];
        int r0 = atomicAdd(&g_deg[d4.x], 1);
        int r1 = atomicAdd(&g_deg[d4.y], 1);
        int r2 = atomicAdd(&g_deg[d4.z], 1);
        int r3 = atomicAdd(&g_deg[d4.w], 1);
        ((int4*)g_rank)[t] = make_int4(r0, r1, r2, r3);
        return;
    }

    // ---- GEMM part: 128 rows/block, 8 warps, mma.sync m16n8k16 fp16->fp32 ----
    __shared__ __half xs[128 * 72];  // 128 rows x 64 halves (stride 72 -> bank rotation)
    __shared__ __half ws[64 * 72];   // 64 W1 k-rows x 64 halves
    __shared__ float sA[128];

    int tid = threadIdx.x;
    int wid = tid >> 5, lane = tid & 31;
    int rowBase = blockIdx.x * 128;
    if (tid < 128) sA[tid] = (tid < 64) ? a1s[tid] : a1d[tid - 64];

    float acc[8][4];
#pragma unroll
    for (int nt = 0; nt < 8; nt++)
#pragma unroll
        for (int c = 0; c < 4; c++) acc[nt][c] = 0.0f;

#pragma unroll 1
    for (int stage = 0; stage < 2; stage++) {
        if (stage) __syncthreads();   // protect smem reuse

        // fill xs: 128 rows x 64 halves (this stage's K-half)
#pragma unroll
        for (int i = 0; i < 8; i++) {
            int idx4 = tid + i * 256;          // 2048 float4 total
            int r = idx4 >> 4;                 // 16 float4 per row
            int k4 = (idx4 & 15) * 4;
            int grow = rowBase + r;
            float4 v = make_float4(0.f, 0.f, 0.f, 0.f);
            if (grow < NN)
                v = __ldg((const float4*)(x + (size_t)grow * 128 + stage * 64 + k4));
            *(__half2*)(&xs[r * 72 + k4])     = __floats2half2_rn(v.x, v.y);
            *(__half2*)(&xs[r * 72 + k4 + 2]) = __floats2half2_rn(v.z, v.w);
        }
        // fill ws: 64 k-rows x 64 halves
#pragma unroll
        for (int i = 0; i < 4; i++) {
            int idx4 = tid + i * 256;          // 1024 float4 total
            int r = idx4 >> 4;
            int k4 = (idx4 & 15) * 4;
            float4 v = __ldg((const float4*)(W1 + (size_t)(stage * 64 + r) * 64 + k4));
            *(__half2*)(&ws[r * 72 + k4])     = __floats2half2_rn(v.x, v.y);
            *(__half2*)(&ws[r * 72 + k4 + 2]) = __floats2half2_rn(v.z, v.w);
        }
        __syncthreads();

#pragma unroll
        for (int kcl = 0; kcl < 4; kcl++) {
            unsigned a0, a1, a2, a3;
            unsigned aaddr = su32(xs) +
                ((wid * 16 + (lane & 15)) * 72 + kcl * 16 + (lane >> 4) * 8) * 2;
            asm volatile(
                "ldmatrix.sync.aligned.m8n8.x4.shared.b16 {%0,%1,%2,%3}, [%4];"
                : "=r"(a0), "=r"(a1), "=r"(a2), "=r"(a3) : "r"(aaddr));
#pragma unroll
            for (int nt = 0; nt < 8; nt++) {
                unsigned b0, b1;
                unsigned baddr = su32(ws) +
                    ((kcl * 16 + (lane & 15)) * 72 + nt * 8) * 2;
                asm volatile(
                    "ldmatrix.sync.aligned.m8n8.x2.trans.shared.b16 {%0,%1}, [%2];"
                    : "=r"(b0), "=r"(b1) : "r"(baddr));
                asm volatile(
                    "mma.sync.aligned.m16n8k16.row.col.f32.f16.f16.f32 "
                    "{%0,%1,%2,%3}, {%4,%5,%6,%7}, {%8,%9}, {%0,%1,%2,%3};"
                    : "+f"(acc[nt][0]), "+f"(acc[nt][1]),
                      "+f"(acc[nt][2]), "+f"(acc[nt][3])
                    : "r"(a0), "r"(a1), "r"(a2), "r"(a3), "r"(b0), "r"(b1));
            }
        }
    }

    // ---- epilogue: store h1 + per-head logits ----
    int q = lane & 3;
    int r0 = rowBase + wid * 16 + (lane >> 2);
    int r1 = r0 + 8;

#pragma unroll
    for (int nt = 0; nt < 8; nt++) {
        int col = nt * 8 + 2 * q;
        if (r0 < NN)
            *(float2*)(g_h1 + (size_t)r0 * 64 + col) = make_float2(acc[nt][0], acc[nt][1]);
        if (r1 < NN)
            *(float2*)(g_h1 + (size_t)r1 * 64 + col) = make_float2(acc[nt][2], acc[nt][3]);
    }

#pragma unroll
    for (int h = 0; h < 8; h++) {
        float as0 = sA[h * 8 + 2 * q], as1v = sA[h * 8 + 2 * q + 1];
        float ad0 = sA[64 + h * 8 + 2 * q], ad1v = sA[64 + h * 8 + 2 * q + 1];
        float s0 = acc[h][0] * as0 + acc[h][1] * as1v;
        float d0 = acc[h][0] * ad0 + acc[h][1] * ad1v;
        float s1 = acc[h][2] * as0 + acc[h][3] * as1v;
        float d1 = acc[h][2] * ad0 + acc[h][3] * ad1v;
#pragma unroll
        for (int o = 1; o <= 2; o <<= 1) {
            s0 += __shfl_xor_sync(FULL, s0, o);
            d0 += __shfl_xor_sync(FULL, d0, o);
            s1 += __shfl_xor_sync(FULL, s1, o);
            d1 += __shfl_xor_sync(FULL, d1, o);
        }
        if (q == 0) {
            if (r0 < NN) { g_as1[r0 * 8 + h] = s0; g_ad1[r0 * 8 + h] = d0; }
            if (r1 < NN) { g_as1[r1 * 8 + h] = s1; g_ad1[r1 * 8 + h] = d1; }
        }
    }
}

// ---------------- scans ----------------
__global__ void s1_scan() {
    __shared__ int sd[SCAN_B];
    int i = blockIdx.x * SCAN_B + threadIdx.x;
    int v = (i < NN) ? g_deg[i] : 0;
    sd[threadIdx.x] = v;
    __syncthreads();
    for (int ofs = 1; ofs < SCAN_B; ofs <<= 1) {
        int t = (threadIdx.x >= ofs) ? sd[threadIdx.x - ofs] : 0;
        __syncthreads();
        sd[threadIdx.x] += t;
        __syncthreads();
    }
    if (i < NN) g_off[i] = sd[threadIdx.x] - v;
    if (threadIdx.x == SCAN_B - 1) g_bsum[blockIdx.x] = sd[threadIdx.x];
}

__global__ void s3_apply() {
    __shared__ int sbase;
    int b = blockIdx.x;
    if (threadIdx.x < 32) {
        int p = 0;
        for (int i = threadIdx.x; i < b; i += 32) p += g_bsum[i];
#pragma unroll
        for (int o = 16; o; o >>= 1) p += __shfl_xor_sync(FULL, p, o);
        if (threadIdx.x == 0) sbase = p;
    }
    __syncthreads();
    int i = b * SCAN_B + threadIdx.x;
    if (i < NN) {
        int o = g_off[i] + sbase;
        g_off[i] = o;
        if (i == NN - 1) g_off[NN] = o + g_deg[i];   // sentinel
        g_deg[i] = 0;                                 // ready for next replay
    }
}

// ---------------- scatter: atomic-free (uses precomputed ranks) ----------------
__global__ void k_scatter(const int* __restrict__ src, const int* __restrict__ dst) {
    int t = blockIdx.x * blockDim.x + threadIdx.x;
    if (t >= EE / 4) return;
    int4 s4 = ((const int4*)src)[t];
    int4 d4 = ((const int4*)dst)[t];
    int4 r4 = ((const int4*)g_rank)[t];
    g_csr[g_off[d4.x] + r4.x] = s4.x;
    g_csr[g_off[d4.y] + r4.y] = s4.y;
    g_csr[g_off[d4.z] + r4.z] = s4.z;
    g_csr[g_off[d4.w] + r4.w] = s4.w;
}

// ---------------- G1: warp-per-dst gather, pipelined ----------------
__global__ void __launch_bounds__(256) g1_gather(const float* __restrict__ b1) {
    int warp = (blockIdx.x * 256 + threadIdx.x) >> 5;
    int lane = threadIdx.x & 31;
    if (warp >= NN) return;
    int n = warp;
    int off = g_off[n];
    int deg = g_off[n + 1] - off;
    int h8 = lane & 7;
    int h4 = lane >> 2;
    float adf = g_ad1[n * 8 + h8];

    float2 acc = make_float2(0.0f, 0.0f);
    float den = 0.0f;

    int sreg = (lane < deg) ? g_csr[off + lane] : 0;

    for (int base = 0; base < deg; base += 32) {
        int sreg_n = 0;
        if (base + 32 < deg) {
            int nl = base + 32 + lane;
            sreg_n = (nl < deg) ? g_csr[off + nl] : 0;
        }
        int cnt = min(32, deg - base);

        int sl0 = __shfl_sync(FULL, sreg, lane >> 3);
        float as = g_as1[sl0 * 8 + h8];

        for (int g = 0; g < cnt; g += 4) {
            float as_n = 0.0f;
            if (g + 4 < cnt) {
                int sln = __shfl_sync(FULL, sreg, g + 4 + (lane >> 3));
                as_n = g_as1[sln * 8 + h8];
            }
            float e = as + adf;
            e = (e >= 0.0f) ? e : NEG_SLOPE * e;
            float p = __expf(e);
            if (base + g + (lane >> 3) >= deg) p = 0.0f;
#pragma unroll
            for (int j = 0; j < 4; j++) {
                int s = __shfl_sync(FULL, sreg, g + j);
                float pj = __shfl_sync(FULL, p, j * 8 + h4);
                float2 v = *(const float2*)(g_h1 + (size_t)s * 64 + 2 * lane);
                acc.x += pj * v.x;
                acc.y += pj * v.y;
                den += pj;
            }
            as = as_n;
        }
        sreg = sreg_n;
    }

    float inv = (den > 0.0f) ? (1.0f / den) : 0.0f;
    float r0 = acc.x * inv + b1[2 * lane];
    float r1 = acc.y * inv + b1[2 * lane + 1];
    r0 = (r0 > 0.0f) ? r0 : (__expf(r0) - 1.0f);
    r1 = (r1 > 0.0f) ? r1 : (__expf(r1) - 1.0f);
    *(float2*)(g_out1 + (size_t)n * 64 + 2 * lane) = make_float2(r0, r1);
}

// ---------------- K5: g2 = elu_h @ W2 (+ layer2 attention logits) ----------------
__global__ void __launch_bounds__(256) k5_gemm2(
    const float* __restrict__ W2, const float* __restrict__ a2s,
    const float* __restrict__ a2d)
{
    __shared__ float sW[64 * 16];
    __shared__ float sA[32];
    for (int i = threadIdx.x; i < 64 * 16; i += blockDim.x) sW[i] = W2[i];
    for (int i = threadIdx.x; i < 32; i += blockDim.x)
        sA[i] = (i < 16) ? a2s[i] : a2d[i - 16];
    __syncthreads();

    int row = blockIdx.x * blockDim.x + threadIdx.x;
    if (row >= NN) return;

    float acc[16];
#pragma unroll
    for (int j = 0; j < 16; j++) acc[j] = 0.0f;

    const float4* x4 = (const float4*)(g_out1 + (size_t)row * 64);
#pragma unroll 1
    for (int kc = 0; kc < 16; kc++) {
        float4 xv = x4[kc];
#pragma unroll
        for (int t = 0; t < 4; t++) {
            float xs = (t == 0) ? xv.x : (t == 1) ? xv.y : (t == 2) ? xv.z : xv.w;
            const float4* wrow = (const float4*)(sW + (kc * 4 + t) * 16);
#pragma unroll
            for (int j4 = 0; j4 < 4; j4++) {
                float4 w = wrow[j4];
                acc[j4 * 4 + 0] += xs * w.x;
                acc[j4 * 4 + 1] += xs * w.y;
                acc[j4 * 4 + 2] += xs * w.z;
                acc[j4 * 4 + 3] += xs * w.w;
            }
        }
    }

    float4* go = (float4*)(g_g2 + (size_t)row * 16);
#pragma unroll
    for (int j4 = 0; j4 < 4; j4++)
        go[j4] = make_float4(acc[j4 * 4], acc[j4 * 4 + 1], acc[j4 * 4 + 2], acc[j4 * 4 + 3]);

    float s = 0.0f, d = 0.0f;
#pragma unroll
    for (int j = 0; j < 16; j++) { s += acc[j] * sA[j]; d += acc[j] * sA[16 + j]; }
    g_as2[row] = s;
    g_ad2[row] = d;
}

// ---------------- G2: warp-per-dst gather, pipelined ----------------
__global__ void __launch_bounds__(256) g2_gather(const float* __restrict__ b2,
                                                 float* __restrict__ out) {
    int warp = (blockIdx.x * 256 + threadIdx.x) >> 5;
    int lane = threadIdx.x & 31;
    if (warp >= NN) return;
    int n = warp;
    int off = g_off[n];
    int deg = g_off[n + 1] - off;
    int half = lane >> 4;
    int d16 = lane & 15;
    float ad = g_ad2[n];

    float acc = 0.0f, den = 0.0f;

    int sreg = (lane < deg) ? g_csr[off + lane] : 0;
    float as = g_as2[sreg];

    for (int base = 0; base < deg; base += 32) {
        int sreg_n = 0;
        float as_n = 0.0f;
        if (base + 32 < deg) {
            int nl = base + 32 + lane;
            sreg_n = (nl < deg) ? g_csr[off + nl] : 0;
            as_n = g_as2[sreg_n];
        }

        float e = as + ad;
        e = (e >= 0.0f) ? e : NEG_SLOPE * e;
        float p = __expf(e);
        if (base + lane >= deg) p = 0.0f;
        int cnt = min(32, deg - base);
        for (int g = 0; g < cnt; g += 2) {
            int s = __shfl_sync(FULL, sreg, g + half);
            float pj = __shfl_sync(FULL, p, g + half);
            float v = g_g2[(size_t)s * 16 + d16];
            acc += pj * v;
            den += pj;
        }
        sreg = sreg_n;
        as = as_n;
    }

    acc += __shfl_xor_sync(FULL, acc, 16);
    den += __shfl_xor_sync(FULL, den, 16);

    float z = ((den > 0.0f) ? (acc / den) : 0.0f) + b2[d16];

    float m = z;
#pragma unroll
    for (int ofs = 1; ofs < 16; ofs <<= 1)
        m = fmaxf(m, __shfl_xor_sync(FULL, m, ofs));
    float sum = __expf(z - m);
#pragma unroll
    for (int ofs = 1; ofs < 16; ofs <<= 1)
        sum += __shfl_xor_sync(FULL, sum, ofs);
    float lse = m + logf(sum);

    if (lane < 16) out[(size_t)n * 16 + d16] = z - lse;
}

// ---------------- launcher ----------------
extern "C" void kernel_launch(void* const* d_in, const int* in_sizes, int n_in,
                              void* d_out, int out_size) {
    const float* x   = (const float*)d_in[0];
    const int*   ei  = (const int*)d_in[1];
    const float* W1  = (const float*)d_in[2];
    const float* a1s = (const float*)d_in[3];
    const float* a1d = (const float*)d_in[4];
    const float* b1  = (const float*)d_in[5];
    const float* W2  = (const float*)d_in[6];
    const float* a2s = (const float*)d_in[7];
    const float* a2d = (const float*)d_in[8];
    const float* b2  = (const float*)d_in[9];
    float* out = (float*)d_out;

    const int* src = ei;
    const int* dst = ei + EE;

    const int TB = 256;
    kA_gemm1_hist<<<TC_BLOCKS + HIST_BLOCKS, TB>>>(x, W1, a1s, a1d, dst);
    s1_scan<<<NBLK, SCAN_B>>>();
    s3_apply<<<NBLK, SCAN_B>>>();
    k_scatter<<<(EE / 4 + TB - 1) / TB, TB>>>(src, dst);
    g1_gather<<<(NN * 32 + TB - 1) / TB, TB>>>(b1);
    k5_gemm2<<<(NN + TB - 1) / TB, TB>>>(W2, a2s, a2d);
    g2_gather<<<(NN * 32 + TB - 1) / TB, TB>>>(b2, out);
}

// round 13
// speedup vs baseline: 1.3976x; 1.0627x over previous
#include <cuda_runtime.h>
#include <cuda_fp16.h>
#include <cuda_bf16.h>
#include <math.h>

#define NN 100000
#define EE 1600000
#define NEG_SLOPE 0.2f
#define SCAN_B 512
#define NBLK ((NN + SCAN_B - 1) / SCAN_B)      // 196
#define TC_BLOCKS ((NN + 127) / 128)            // 782 (tensor-core GEMM blocks)
#define HIST_BLOCKS ((EE / 4 + 255) / 256)      // 1563
#define FULL 0xFFFFFFFFu

// ---------------- scratch (device globals) ----------------
__device__ float g_h1[NN * 64];     // layer1 GEMM output [N,H*D]
__device__ float g_as1[NN * 8];
__device__ float g_ad1[NN * 8];
__device__ float g_out1[NN * 64];   // layer1 final (ELU'd)
__device__ float g_g2[NN * 16];     // layer2 GEMM output
__device__ float g_as2[NN];
__device__ float g_ad2[NN];
__device__ int   g_deg[NN];         // zero at load; self-reset by s3 each call
__device__ int   g_off[NN + 1];     // CSR offsets, sentinel off[NN]=EE
__device__ int   g_rank[EE];        // per-edge rank within its dst segment
__device__ int   g_csr[EE];         // src node ids, grouped by dst
__device__ int   g_bsum[NBLK];

__device__ __forceinline__ unsigned su32(const void* p) {
    return (unsigned)__cvta_generic_to_shared(p);
}

// ---------------- KA: tensor-core GEMM1 (+logits) fused with degree histogram ----------------
__global__ void __launch_bounds__(256) kA_gemm1_hist(
    const float* __restrict__ x, const float* __restrict__ W1,
    const float* __restrict__ a1s, const float* __restrict__ a1d,
    const int* __restrict__ dst)
{
    if (blockIdx.x >= TC_BLOCKS) {
        // ---- histogram part: 4 edges/thread, record ranks ----
        int t = (blockIdx.x - TC_BLOCKS) * 256 + threadIdx.x;
        if (t >= EE / 4) return;
        int4 d4 = ((const int4*)dst)[t];
        int r0 = atomicAdd(&g_deg[d4.x], 1);
        int r1 = atomicAdd(&g_deg[d4.y], 1);
        int r2 = atomicAdd(&g_deg[d4.z], 1);
        int r3 = atomicAdd(&g_deg[d4.w], 1);
        ((int4*)g_rank)[t] = make_int4(r0, r1, r2, r3);
        return;
    }

    // ---- GEMM part: 128 rows/block, 8 warps, mma.sync m16n8k16 fp16->fp32 ----
    __shared__ __half xs[128 * 72];  // 128 rows x 64 halves (stride 72 -> bank rotation)
    __shared__ __half ws[64 * 72];   // 64 W1 k-rows x 64 halves
    __shared__ float sA[128];

    int tid = threadIdx.x;
    int wid = tid >> 5, lane = tid & 31;
    int rowBase = blockIdx.x * 128;
    if (tid < 128) sA[tid] = (tid < 64) ? a1s[tid] : a1d[tid - 64];

    float acc[8][4];
#pragma unroll
    for (int nt = 0; nt < 8; nt++)
#pragma unroll
        for (int c = 0; c < 4; c++) acc[nt][c] = 0.0f;

#pragma unroll 1
    for (int stage = 0; stage < 2; stage++) {
        if (stage) __syncthreads();   // protect smem reuse

#pragma unroll
        for (int i = 0; i < 8; i++) {
            int idx4 = tid + i * 256;          // 2048 float4 total
            int r = idx4 >> 4;                 // 16 float4 per row
            int k4 = (idx4 & 15) * 4;
            int grow = rowBase + r;
            float4 v = make_float4(0.f, 0.f, 0.f, 0.f);
            if (grow < NN)
                v = __ldg((const float4*)(x + (size_t)grow * 128 + stage * 64 + k4));
            *(__half2*)(&xs[r * 72 + k4])     = __floats2half2_rn(v.x, v.y);
            *(__half2*)(&xs[r * 72 + k4 + 2]) = __floats2half2_rn(v.z, v.w);
        }
#pragma unroll
        for (int i = 0; i < 4; i++) {
            int idx4 = tid + i * 256;          // 1024 float4 total
            int r = idx4 >> 4;
            int k4 = (idx4 & 15) * 4;
            float4 v = __ldg((const float4*)(W1 + (size_t)(stage * 64 + r) * 64 + k4));
            *(__half2*)(&ws[r * 72 + k4])     = __floats2half2_rn(v.x, v.y);
            *(__half2*)(&ws[r * 72 + k4 + 2]) = __floats2half2_rn(v.z, v.w);
        }
        __syncthreads();

#pragma unroll
        for (int kcl = 0; kcl < 4; kcl++) {
            unsigned a0, a1, a2, a3;
            unsigned aaddr = su32(xs) +
                ((wid * 16 + (lane & 15)) * 72 + kcl * 16 + (lane >> 4) * 8) * 2;
            asm volatile(
                "ldmatrix.sync.aligned.m8n8.x4.shared.b16 {%0,%1,%2,%3}, [%4];"
                : "=r"(a0), "=r"(a1), "=r"(a2), "=r"(a3) : "r"(aaddr));
#pragma unroll
            for (int nt = 0; nt < 8; nt++) {
                unsigned b0, b1;
                unsigned baddr = su32(ws) +
                    ((kcl * 16 + (lane & 15)) * 72 + nt * 8) * 2;
                asm volatile(
                    "ldmatrix.sync.aligned.m8n8.x2.trans.shared.b16 {%0,%1}, [%2];"
                    : "=r"(b0), "=r"(b1) : "r"(baddr));
                asm volatile(
                    "mma.sync.aligned.m16n8k16.row.col.f32.f16.f16.f32 "
                    "{%0,%1,%2,%3}, {%4,%5,%6,%7}, {%8,%9}, {%0,%1,%2,%3};"
                    : "+f"(acc[nt][0]), "+f"(acc[nt][1]),
                      "+f"(acc[nt][2]), "+f"(acc[nt][3])
                    : "r"(a0), "r"(a1), "r"(a2), "r"(a3), "r"(b0), "r"(b1));
            }
        }
    }

    // ---- epilogue: store h1 + per-head logits ----
    int q = lane & 3;
    int r0 = rowBase + wid * 16 + (lane >> 2);
    int r1 = r0 + 8;

#pragma unroll
    for (int nt = 0; nt < 8; nt++) {
        int col = nt * 8 + 2 * q;
        if (r0 < NN)
            *(float2*)(g_h1 + (size_t)r0 * 64 + col) = make_float2(acc[nt][0], acc[nt][1]);
        if (r1 < NN)
            *(float2*)(g_h1 + (size_t)r1 * 64 + col) = make_float2(acc[nt][2], acc[nt][3]);
    }

#pragma unroll
    for (int h = 0; h < 8; h++) {
        float as0 = sA[h * 8 + 2 * q], as1v = sA[h * 8 + 2 * q + 1];
        float ad0 = sA[64 + h * 8 + 2 * q], ad1v = sA[64 + h * 8 + 2 * q + 1];
        float s0 = acc[h][0] * as0 + acc[h][1] * as1v;
        float d0 = acc[h][0] * ad0 + acc[h][1] * ad1v;
        float s1 = acc[h][2] * as0 + acc[h][3] * as1v;
        float d1 = acc[h][2] * ad0 + acc[h][3] * ad1v;
#pragma unroll
        for (int o = 1; o <= 2; o <<= 1) {
            s0 += __shfl_xor_sync(FULL, s0, o);
            d0 += __shfl_xor_sync(FULL, d0, o);
            s1 += __shfl_xor_sync(FULL, s1, o);
            d1 += __shfl_xor_sync(FULL, d1, o);
        }
        if (q == 0) {
            if (r0 < NN) { g_as1[r0 * 8 + h] = s0; g_ad1[r0 * 8 + h] = d0; }
            if (r1 < NN) { g_as1[r1 * 8 + h] = s1; g_ad1[r1 * 8 + h] = d1; }
        }
    }
}

// ---------------- scans ----------------
__global__ void s1_scan() {
    __shared__ int sd[SCAN_B];
    int i = blockIdx.x * SCAN_B + threadIdx.x;
    int v = (i < NN) ? g_deg[i] : 0;
    sd[threadIdx.x] = v;
    __syncthreads();
    for (int ofs = 1; ofs < SCAN_B; ofs <<= 1) {
        int t = (threadIdx.x >= ofs) ? sd[threadIdx.x - ofs] : 0;
        __syncthreads();
        sd[threadIdx.x] += t;
        __syncthreads();
    }
    if (i < NN) g_off[i] = sd[threadIdx.x] - v;
    if (threadIdx.x == SCAN_B - 1) g_bsum[blockIdx.x] = sd[threadIdx.x];
}

__global__ void s3_apply() {
    __shared__ int sbase;
    int b = blockIdx.x;
    if (threadIdx.x < 32) {
        int p = 0;
        for (int i = threadIdx.x; i < b; i += 32) p += g_bsum[i];
#pragma unroll
        for (int o = 16; o; o >>= 1) p += __shfl_xor_sync(FULL, p, o);
        if (threadIdx.x == 0) sbase = p;
    }
    __syncthreads();
    int i = b * SCAN_B + threadIdx.x;
    if (i < NN) {
        int o = g_off[i] + sbase;
        g_off[i] = o;
        if (i == NN - 1) g_off[NN] = o + g_deg[i];   // sentinel
        g_deg[i] = 0;                                 // ready for next replay
    }
}

// ---------------- scatter: atomic-free (uses precomputed ranks) ----------------
__global__ void k_scatter(const int* __restrict__ src, const int* __restrict__ dst) {
    int t = blockIdx.x * blockDim.x + threadIdx.x;
    if (t >= EE / 4) return;
    int4 s4 = ((const int4*)src)[t];
    int4 d4 = ((const int4*)dst)[t];
    int4 r4 = ((const int4*)g_rank)[t];
    g_csr[g_off[d4.x] + r4.x] = s4.x;
    g_csr[g_off[d4.y] + r4.y] = s4.y;
    g_csr[g_off[d4.z] + r4.z] = s4.z;
    g_csr[g_off[d4.w] + r4.w] = s4.w;
}

// ---------------- G1: warp-per-dst gather, pipelined ----------------
__global__ void __launch_bounds__(256) g1_gather(const float* __restrict__ b1) {
    int warp = (blockIdx.x * 256 + threadIdx.x) >> 5;
    int lane = threadIdx.x & 31;
    if (warp >= NN) return;
    int n = warp;
    int off = g_off[n];
    int deg = g_off[n + 1] - off;
    int h8 = lane & 7;
    int h4 = lane >> 2;
    float adf = g_ad1[n * 8 + h8];

    float2 acc = make_float2(0.0f, 0.0f);
    float den = 0.0f;

    int sreg = (lane < deg) ? g_csr[off + lane] : 0;

    for (int base = 0; base < deg; base += 32) {
        int sreg_n = 0;
        if (base + 32 < deg) {
            int nl = base + 32 + lane;
            sreg_n = (nl < deg) ? g_csr[off + nl] : 0;
        }
        int cnt = min(32, deg - base);

        int sl0 = __shfl_sync(FULL, sreg, lane >> 3);
        float as = g_as1[sl0 * 8 + h8];

        for (int g = 0; g < cnt; g += 4) {
            float as_n = 0.0f;
            if (g + 4 < cnt) {
                int sln = __shfl_sync(FULL, sreg, g + 4 + (lane >> 3));
                as_n = g_as1[sln * 8 + h8];
            }
            float e = as + adf;
            e = (e >= 0.0f) ? e : NEG_SLOPE * e;
            float p = __expf(e);
            if (base + g + (lane >> 3) >= deg) p = 0.0f;
#pragma unroll
            for (int j = 0; j < 4; j++) {
                int s = __shfl_sync(FULL, sreg, g + j);
                float pj = __shfl_sync(FULL, p, j * 8 + h4);
                float2 v = *(const float2*)(g_h1 + (size_t)s * 64 + 2 * lane);
                acc.x += pj * v.x;
                acc.y += pj * v.y;
                den += pj;
            }
            as = as_n;
        }
        sreg = sreg_n;
    }

    float inv = (den > 0.0f) ? (1.0f / den) : 0.0f;
    float r0 = acc.x * inv + b1[2 * lane];
    float r1 = acc.y * inv + b1[2 * lane + 1];
    r0 = (r0 > 0.0f) ? r0 : (__expf(r0) - 1.0f);
    r1 = (r1 > 0.0f) ? r1 : (__expf(r1) - 1.0f);
    *(float2*)(g_out1 + (size_t)n * 64 + 2 * lane) = make_float2(r0, r1);
}

// ---------------- K5: tensor-core GEMM2 (+layer2 attention logits) ----------------
__global__ void __launch_bounds__(256) k5_gemm2(
    const float* __restrict__ W2, const float* __restrict__ a2s,
    const float* __restrict__ a2d)
{
    __shared__ __half xs[128 * 72];  // 128 rows x 64 halves (stride 72)
    __shared__ __half ws[64 * 24];   // 64 k-rows x 16 halves (stride 24 -> 48B)
    __shared__ float sA[32];

    int tid = threadIdx.x;
    int wid = tid >> 5, lane = tid & 31;
    int rowBase = blockIdx.x * 128;
    if (tid < 32) sA[tid] = (tid < 16) ? a2s[tid] : a2d[tid - 16];

    // load g_out1 rows -> xs (fp16)
#pragma unroll
    for (int i = 0; i < 8; i++) {
        int idx4 = tid + i * 256;          // 2048 float4 total
        int r = idx4 >> 4;
        int k4 = (idx4 & 15) * 4;
        int grow = rowBase + r;
        float4 v = make_float4(0.f, 0.f, 0.f, 0.f);
        if (grow < NN)
            v = *(const float4*)(g_out1 + (size_t)grow * 64 + k4);
        *(__half2*)(&xs[r * 72 + k4])     = __floats2half2_rn(v.x, v.y);
        *(__half2*)(&xs[r * 72 + k4 + 2]) = __floats2half2_rn(v.z, v.w);
    }
    // load W2 -> ws (fp16): 64 k-rows x 16 cols = 256 float4
    if (tid < 256) {
        int r = tid >> 2;                  // 4 float4 per row
        int k4 = (tid & 3) * 4;
        float4 v = __ldg((const float4*)(W2 + (size_t)r * 16 + k4));
        *(__half2*)(&ws[r * 24 + k4])     = __floats2half2_rn(v.x, v.y);
        *(__half2*)(&ws[r * 24 + k4 + 2]) = __floats2half2_rn(v.z, v.w);
    }
    __syncthreads();

    float acc[2][4];
#pragma unroll
    for (int nt = 0; nt < 2; nt++)
#pragma unroll
        for (int c = 0; c < 4; c++) acc[nt][c] = 0.0f;

#pragma unroll
    for (int kcl = 0; kcl < 4; kcl++) {
        unsigned a0, a1, a2, a3;
        unsigned aaddr = su32(xs) +
            ((wid * 16 + (lane & 15)) * 72 + kcl * 16 + (lane >> 4) * 8) * 2;
        asm volatile(
            "ldmatrix.sync.aligned.m8n8.x4.shared.b16 {%0,%1,%2,%3}, [%4];"
            : "=r"(a0), "=r"(a1), "=r"(a2), "=r"(a3) : "r"(aaddr));
#pragma unroll
        for (int nt = 0; nt < 2; nt++) {
            unsigned b0, b1;
            unsigned baddr = su32(ws) +
                ((kcl * 16 + (lane & 15)) * 24 + nt * 8) * 2;
            asm volatile(
                "ldmatrix.sync.aligned.m8n8.x2.trans.shared.b16 {%0,%1}, [%2];"
                : "=r"(b0), "=r"(b1) : "r"(baddr));
            asm volatile(
                "mma.sync.aligned.m16n8k16.row.col.f32.f16.f16.f32 "
                "{%0,%1,%2,%3}, {%4,%5,%6,%7}, {%8,%9}, {%0,%1,%2,%3};"
                : "+f"(acc[nt][0]), "+f"(acc[nt][1]),
                  "+f"(acc[nt][2]), "+f"(acc[nt][3])
                : "r"(a0), "r"(a1), "r"(a2), "r"(a3), "r"(b0), "r"(b1));
        }
    }

    // ---- epilogue: store g2 + layer2 logits ----
    int q = lane & 3;
    int r0 = rowBase + wid * 16 + (lane >> 2);
    int r1 = r0 + 8;

#pragma unroll
    for (int nt = 0; nt < 2; nt++) {
        int col = nt * 8 + 2 * q;
        if (r0 < NN)
            *(float2*)(g_g2 + (size_t)r0 * 16 + col) = make_float2(acc[nt][0], acc[nt][1]);
        if (r1 < NN)
            *(float2*)(g_g2 + (size_t)r1 * 16 + col) = make_float2(acc[nt][2], acc[nt][3]);
    }

    float s0 = 0.0f, d0 = 0.0f, s1 = 0.0f, d1 = 0.0f;
#pragma unroll
    for (int nt = 0; nt < 2; nt++) {
        int c0 = nt * 8 + 2 * q, c1 = c0 + 1;
        s0 += acc[nt][0] * sA[c0] + acc[nt][1] * sA[c1];
        d0 += acc[nt][0] * sA[16 + c0] + acc[nt][1] * sA[16 + c1];
        s1 += acc[nt][2] * sA[c0] + acc[nt][3] * sA[c1];
        d1 += acc[nt][2] * sA[16 + c0] + acc[nt][3] * sA[16 + c1];
    }
#pragma unroll
    for (int o = 1; o <= 2; o <<= 1) {
        s0 += __shfl_xor_sync(FULL, s0, o);
        d0 += __shfl_xor_sync(FULL, d0, o);
        s1 += __shfl_xor_sync(FULL, s1, o);
        d1 += __shfl_xor_sync(FULL, d1, o);
    }
    if (q == 0) {
        if (r0 < NN) { g_as2[r0] = s0; g_ad2[r0] = d0; }
        if (r1 < NN) { g_as2[r1] = s1; g_ad2[r1] = d1; }
    }
}

// ---------------- G2: warp-per-dst gather, pipelined ----------------
__global__ void __launch_bounds__(256) g2_gather(const float* __restrict__ b2,
                                                 float* __restrict__ out) {
    int warp = (blockIdx.x * 256 + threadIdx.x) >> 5;
    int lane = threadIdx.x & 31;
    if (warp >= NN) return;
    int n = warp;
    int off = g_off[n];
    int deg = g_off[n + 1] - off;
    int half = lane >> 4;
    int d16 = lane & 15;
    float ad = g_ad2[n];

    float acc = 0.0f, den = 0.0f;

    int sreg = (lane < deg) ? g_csr[off + lane] : 0;
    float as = g_as2[sreg];

    for (int base = 0; base < deg; base += 32) {
        int sreg_n = 0;
        float as_n = 0.0f;
        if (base + 32 < deg) {
            int nl = base + 32 + lane;
            sreg_n = (nl < deg) ? g_csr[off + nl] : 0;
            as_n = g_as2[sreg_n];
        }

        float e = as + ad;
        e = (e >= 0.0f) ? e : NEG_SLOPE * e;
        float p = __expf(e);
        if (base + lane >= deg) p = 0.0f;
        int cnt = min(32, deg - base);
        for (int g = 0; g < cnt; g += 2) {
            int s = __shfl_sync(FULL, sreg, g + half);
            float pj = __shfl_sync(FULL, p, g + half);
            float v = g_g2[(size_t)s * 16 + d16];
            acc += pj * v;
            den += pj;
        }
        sreg = sreg_n;
        as = as_n;
    }

    acc += __shfl_xor_sync(FULL, acc, 16);
    den += __shfl_xor_sync(FULL, den, 16);

    float z = ((den > 0.0f) ? (acc / den) : 0.0f) + b2[d16];

    float m = z;
#pragma unroll
    for (int ofs = 1; ofs < 16; ofs <<= 1)
        m = fmaxf(m, __shfl_xor_sync(FULL, m, ofs));
    float sum = __expf(z - m);
#pragma unroll
    for (int ofs = 1; ofs < 16; ofs <<= 1)
        sum += __shfl_xor_sync(FULL, sum, ofs);
    float lse = m + logf(sum);

    if (lane < 16) out[(size_t)n * 16 + d16] = z - lse;
}

// ---------------- launcher ----------------
extern "C" void kernel_launch(void* const* d_in, const int* in_sizes, int n_in,
                              void* d_out, int out_size) {
    const float* x   = (const float*)d_in[0];
    const int*   ei  = (const int*)d_in[1];
    const float* W1  = (const float*)d_in[2];
    const float* a1s = (const float*)d_in[3];
    const float* a1d = (const float*)d_in[4];
    const float* b1  = (const float*)d_in[5];
    const float* W2  = (const float*)d_in[6];
    const float* a2s = (const float*)d_in[7];
    const float* a2d = (const float*)d_in[8];
    const float* b2  = (const float*)d_in[9];
    float* out = (float*)d_out;

    const int* src = ei;
    const int* dst = ei + EE;

    const int TB = 256;
    kA_gemm1_hist<<<TC_BLOCKS + HIST_BLOCKS, TB>>>(x, W1, a1s, a1d, dst);
    s1_scan<<<NBLK, SCAN_B>>>();
    s3_apply<<<NBLK, SCAN_B>>>();
    k_scatter<<<(EE / 4 + TB - 1) / TB, TB>>>(src, dst);
    g1_gather<<<(NN * 32 + TB - 1) / TB, TB>>>(b1);
    k5_gemm2<<<TC_BLOCKS, TB>>>(W2, a2s, a2d);
    g2_gather<<<(NN * 32 + TB - 1) / TB, TB>>>(b2, out);
}

// round 14
// speedup vs baseline: 1.4238x; 1.0188x over previous
#include <cuda_runtime.h>
#include <cuda_fp16.h>
#include <cuda_bf16.h>
#include <math.h>

#define NN 100000
#define EE 1600000
#define NEG_SLOPE 0.2f
#define SCAN_B 512
#define NBLK ((NN + SCAN_B - 1) / SCAN_B)      // 196
#define TC_BLOCKS ((NN + 127) / 128)            // 782 (tensor-core GEMM blocks)
#define HIST_BLOCKS ((EE / 4 + 255) / 256)      // 1563
#define FULL 0xFFFFFFFFu

// ---------------- scratch (device globals) ----------------
__device__ float g_h1[NN * 64];     // layer1 GEMM output [N,H*D]
__device__ float g_as1[NN * 8];
__device__ float g_ad1[NN * 8];
__device__ float g_out1[NN * 64];   // layer1 final (ELU'd)
__device__ float g_g2[NN * 16];     // layer2 GEMM output
__device__ float g_as2[NN];
__device__ float g_ad2[NN];
__device__ int   g_deg[NN];         // zero at load; self-reset by s3 each call
__device__ int   g_off[NN + 1];     // CSR offsets, sentinel off[NN]=EE
__device__ int   g_rank[EE];        // per-edge rank within its dst segment
__device__ int   g_csr[EE];         // src node ids, grouped by dst
__device__ int   g_bsum[NBLK];

__device__ __forceinline__ unsigned su32(const void* p) {
    return (unsigned)__cvta_generic_to_shared(p);
}

// ---------------- KA: tensor-core GEMM1 (+logits) fused with degree histogram ----------------
__global__ void __launch_bounds__(256) kA_gemm1_hist(
    const float* __restrict__ x, const float* __restrict__ W1,
    const float* __restrict__ a1s, const float* __restrict__ a1d,
    const int* __restrict__ dst)
{
    if (blockIdx.x >= TC_BLOCKS) {
        // ---- histogram part: 4 edges/thread, record ranks ----
        int t = (blockIdx.x - TC_BLOCKS) * 256 + threadIdx.x;
        if (t >= EE / 4) return;
        int4 d4 = ((const int4*)dst)[t];
        int r0 = atomicAdd(&g_deg[d4.x], 1);
        int r1 = atomicAdd(&g_deg[d4.y], 1);
        int r2 = atomicAdd(&g_deg[d4.z], 1);
        int r3 = atomicAdd(&g_deg[d4.w], 1);
        ((int4*)g_rank)[t] = make_int4(r0, r1, r2, r3);
        return;
    }

    // ---- GEMM part: 128 rows/block, 8 warps, mma.sync m16n8k16 fp16->fp32 ----
    __shared__ __half xs[128 * 72];  // 128 rows x 64 halves (stride 72 -> bank rotation)
    __shared__ __half ws[64 * 72];   // 64 W1 k-rows x 64 halves
    __shared__ float sA[128];

    int tid = threadIdx.x;
    int wid = tid >> 5, lane = tid & 31;
    int rowBase = blockIdx.x * 128;
    if (tid < 128) sA[tid] = (tid < 64) ? a1s[tid] : a1d[tid - 64];

    float acc[8][4];
#pragma unroll
    for (int nt = 0; nt < 8; nt++)
#pragma unroll
        for (int c = 0; c < 4; c++) acc[nt][c] = 0.0f;

#pragma unroll 1
    for (int stage = 0; stage < 2; stage++) {
        if (stage) __syncthreads();   // protect smem reuse

#pragma unroll
        for (int i = 0; i < 8; i++) {
            int idx4 = tid + i * 256;          // 2048 float4 total
            int r = idx4 >> 4;                 // 16 float4 per row
            int k4 = (idx4 & 15) * 4;
            int grow = rowBase + r;
            float4 v = make_float4(0.f, 0.f, 0.f, 0.f);
            if (grow < NN)
                v = __ldg((const float4*)(x + (size_t)grow * 128 + stage * 64 + k4));
            *(__half2*)(&xs[r * 72 + k4])     = __floats2half2_rn(v.x, v.y);
            *(__half2*)(&xs[r * 72 + k4 + 2]) = __floats2half2_rn(v.z, v.w);
        }
#pragma unroll
        for (int i = 0; i < 4; i++) {
            int idx4 = tid + i * 256;          // 1024 float4 total
            int r = idx4 >> 4;
            int k4 = (idx4 & 15) * 4;
            float4 v = __ldg((const float4*)(W1 + (size_t)(stage * 64 + r) * 64 + k4));
            *(__half2*)(&ws[r * 72 + k4])     = __floats2half2_rn(v.x, v.y);
            *(__half2*)(&ws[r * 72 + k4 + 2]) = __floats2half2_rn(v.z, v.w);
        }
        __syncthreads();

#pragma unroll
        for (int kcl = 0; kcl < 4; kcl++) {
            unsigned a0, a1, a2, a3;
            unsigned aaddr = su32(xs) +
                ((wid * 16 + (lane & 15)) * 72 + kcl * 16 + (lane >> 4) * 8) * 2;
            asm volatile(
                "ldmatrix.sync.aligned.m8n8.x4.shared.b16 {%0,%1,%2,%3}, [%4];"
                : "=r"(a0), "=r"(a1), "=r"(a2), "=r"(a3) : "r"(aaddr));
#pragma unroll
            for (int nt = 0; nt < 8; nt++) {
                unsigned b0, b1;
                unsigned baddr = su32(ws) +
                    ((kcl * 16 + (lane & 15)) * 72 + nt * 8) * 2;
                asm volatile(
                    "ldmatrix.sync.aligned.m8n8.x2.trans.shared.b16 {%0,%1}, [%2];"
                    : "=r"(b0), "=r"(b1) : "r"(baddr));
                asm volatile(
                    "mma.sync.aligned.m16n8k16.row.col.f32.f16.f16.f32 "
                    "{%0,%1,%2,%3}, {%4,%5,%6,%7}, {%8,%9}, {%0,%1,%2,%3};"
                    : "+f"(acc[nt][0]), "+f"(acc[nt][1]),
                      "+f"(acc[nt][2]), "+f"(acc[nt][3])
                    : "r"(a0), "r"(a1), "r"(a2), "r"(a3), "r"(b0), "r"(b1));
            }
        }
    }

    // ---- epilogue: store h1 + per-head logits ----
    int q = lane & 3;
    int r0 = rowBase + wid * 16 + (lane >> 2);
    int r1 = r0 + 8;

#pragma unroll
    for (int nt = 0; nt < 8; nt++) {
        int col = nt * 8 + 2 * q;
        if (r0 < NN)
            *(float2*)(g_h1 + (size_t)r0 * 64 + col) = make_float2(acc[nt][0], acc[nt][1]);
        if (r1 < NN)
            *(float2*)(g_h1 + (size_t)r1 * 64 + col) = make_float2(acc[nt][2], acc[nt][3]);
    }

#pragma unroll
    for (int h = 0; h < 8; h++) {
        float as0 = sA[h * 8 + 2 * q], as1v = sA[h * 8 + 2 * q + 1];
        float ad0 = sA[64 + h * 8 + 2 * q], ad1v = sA[64 + h * 8 + 2 * q + 1];
        float s0 = acc[h][0] * as0 + acc[h][1] * as1v;
        float d0 = acc[h][0] * ad0 + acc[h][1] * ad1v;
        float s1 = acc[h][2] * as0 + acc[h][3] * as1v;
        float d1 = acc[h][2] * ad0 + acc[h][3] * ad1v;
#pragma unroll
        for (int o = 1; o <= 2; o <<= 1) {
            s0 += __shfl_xor_sync(FULL, s0, o);
            d0 += __shfl_xor_sync(FULL, d0, o);
            s1 += __shfl_xor_sync(FULL, s1, o);
            d1 += __shfl_xor_sync(FULL, d1, o);
        }
        if (q == 0) {
            if (r0 < NN) { g_as1[r0 * 8 + h] = s0; g_ad1[r0 * 8 + h] = d0; }
            if (r1 < NN) { g_as1[r1 * 8 + h] = s1; g_ad1[r1 * 8 + h] = d1; }
        }
    }
}

// ---------------- scans ----------------
__global__ void s1_scan() {
    __shared__ int sd[SCAN_B];
    int i = blockIdx.x * SCAN_B + threadIdx.x;
    int v = (i < NN) ? g_deg[i] : 0;
    sd[threadIdx.x] = v;
    __syncthreads();
    for (int ofs = 1; ofs < SCAN_B; ofs <<= 1) {
        int t = (threadIdx.x >= ofs) ? sd[threadIdx.x - ofs] : 0;
        __syncthreads();
        sd[threadIdx.x] += t;
        __syncthreads();
    }
    if (i < NN) g_off[i] = sd[threadIdx.x] - v;
    if (threadIdx.x == SCAN_B - 1) g_bsum[blockIdx.x] = sd[threadIdx.x];
}

__global__ void s3_apply() {
    __shared__ int sbase;
    int b = blockIdx.x;
    if (threadIdx.x < 32) {
        int p = 0;
        for (int i = threadIdx.x; i < b; i += 32) p += g_bsum[i];
#pragma unroll
        for (int o = 16; o; o >>= 1) p += __shfl_xor_sync(FULL, p, o);
        if (threadIdx.x == 0) sbase = p;
    }
    __syncthreads();
    int i = b * SCAN_B + threadIdx.x;
    if (i < NN) {
        int o = g_off[i] + sbase;
        g_off[i] = o;
        if (i == NN - 1) g_off[NN] = o + g_deg[i];   // sentinel
        g_deg[i] = 0;                                 // ready for next replay
    }
}

// ---------------- scatter: atomic-free (uses precomputed ranks) ----------------
__global__ void k_scatter(const int* __restrict__ src, const int* __restrict__ dst) {
    int t = blockIdx.x * blockDim.x + threadIdx.x;
    if (t >= EE / 4) return;
    int4 s4 = ((const int4*)src)[t];
    int4 d4 = ((const int4*)dst)[t];
    int4 r4 = ((const int4*)g_rank)[t];
    g_csr[g_off[d4.x] + r4.x] = s4.x;
    g_csr[g_off[d4.y] + r4.y] = s4.y;
    g_csr[g_off[d4.z] + r4.z] = s4.z;
    g_csr[g_off[d4.w] + r4.w] = s4.w;
}

// ---------------- G1: warp-per-dst gather, 8 edges in flight ----------------
__global__ void __launch_bounds__(256) g1_gather(const float* __restrict__ b1) {
    int warp = (blockIdx.x * 256 + threadIdx.x) >> 5;
    int lane = threadIdx.x & 31;
    if (warp >= NN) return;
    int n = warp;
    int off = g_off[n];
    int deg = g_off[n + 1] - off;
    int h8 = lane & 7;            // head index in logit phase
    int h4 = lane >> 2;           // head owning this lane's 2 dims
    float adf = g_ad1[n * 8 + h8];

    float2 acc = make_float2(0.0f, 0.0f);
    float den = 0.0f;

    int sreg = (lane < deg) ? g_csr[off + lane] : 0;

    for (int base = 0; base < deg; base += 32) {
        int sreg_n = 0;
        if (base + 32 < deg) {                       // warp-uniform
            int nl = base + 32 + lane;
            sreg_n = (nl < deg) ? g_csr[off + nl] : 0;
        }
        int cnt = min(32, deg - base);

        // prefetch group 0's logit operand
        int sl0 = __shfl_sync(FULL, sreg, lane >> 3);
        float as = g_as1[sl0 * 8 + h8];

        for (int g = 0; g < cnt; g += 8) {
            bool hasB = (g + 4 < cnt);               // warp-uniform
            float asB = 0.0f;
            if (hasB) {
                int slB = __shfl_sync(FULL, sreg, g + 4 + (lane >> 3));
                asB = g_as1[slB * 8 + h8];
            }
            float as_nx = 0.0f;
            if (g + 8 < cnt) {                       // warp-uniform
                int slN = __shfl_sync(FULL, sreg, g + 8 + (lane >> 3));
                as_nx = g_as1[slN * 8 + h8];
            }

            float eA = as + adf;
            eA = (eA >= 0.0f) ? eA : NEG_SLOPE * eA;
            float pA = __expf(eA);
            if (base + g + (lane >> 3) >= deg) pA = 0.0f;

            float pB = 0.0f;
            if (hasB) {
                float eB = asB + adf;
                eB = (eB >= 0.0f) ? eB : NEG_SLOPE * eB;
                pB = __expf(eB);
                if (base + g + 4 + (lane >> 3) >= deg) pB = 0.0f;
            }

            // issue all 8 h1 loads before consuming any
            float2 v[8];
            float pj[8];
#pragma unroll
            for (int j = 0; j < 4; j++) {
                int s = __shfl_sync(FULL, sreg, g + j);
                pj[j] = __shfl_sync(FULL, pA, j * 8 + h4);
                v[j] = *(const float2*)(g_h1 + (size_t)s * 64 + 2 * lane);
            }
#pragma unroll
            for (int j = 0; j < 4; j++) {
                int s = __shfl_sync(FULL, sreg, g + 4 + j);
                pj[4 + j] = __shfl_sync(FULL, pB, j * 8 + h4);
                v[4 + j] = *(const float2*)(g_h1 + (size_t)s * 64 + 2 * lane);
            }
#pragma unroll
            for (int j = 0; j < 8; j++) {
                acc.x += pj[j] * v[j].x;
                acc.y += pj[j] * v[j].y;
                den += pj[j];
            }
            as = as_nx;
        }
        sreg = sreg_n;
    }

    float inv = (den > 0.0f) ? (1.0f / den) : 0.0f;
    float r0 = acc.x * inv + b1[2 * lane];
    float r1 = acc.y * inv + b1[2 * lane + 1];
    r0 = (r0 > 0.0f) ? r0 : (__expf(r0) - 1.0f);
    r1 = (r1 > 0.0f) ? r1 : (__expf(r1) - 1.0f);
    *(float2*)(g_out1 + (size_t)n * 64 + 2 * lane) = make_float2(r0, r1);
}

// ---------------- K5: tensor-core GEMM2 (+layer2 attention logits) ----------------
__global__ void __launch_bounds__(256) k5_gemm2(
    const float* __restrict__ W2, const float* __restrict__ a2s,
    const float* __restrict__ a2d)
{
    __shared__ __half xs[128 * 72];  // 128 rows x 64 halves (stride 72)
    __shared__ __half ws[64 * 24];   // 64 k-rows x 16 halves (stride 24 -> 48B)
    __shared__ float sA[32];

    int tid = threadIdx.x;
    int wid = tid >> 5, lane = tid & 31;
    int rowBase = blockIdx.x * 128;
    if (tid < 32) sA[tid] = (tid < 16) ? a2s[tid] : a2d[tid - 16];

#pragma unroll
    for (int i = 0; i < 8; i++) {
        int idx4 = tid + i * 256;
        int r = idx4 >> 4;
        int k4 = (idx4 & 15) * 4;
        int grow = rowBase + r;
        float4 v = make_float4(0.f, 0.f, 0.f, 0.f);
        if (grow < NN)
            v = *(const float4*)(g_out1 + (size_t)grow * 64 + k4);
        *(__half2*)(&xs[r * 72 + k4])     = __floats2half2_rn(v.x, v.y);
        *(__half2*)(&xs[r * 72 + k4 + 2]) = __floats2half2_rn(v.z, v.w);
    }
    if (tid < 256) {
        int r = tid >> 2;
        int k4 = (tid & 3) * 4;
        float4 v = __ldg((const float4*)(W2 + (size_t)r * 16 + k4));
        *(__half2*)(&ws[r * 24 + k4])     = __floats2half2_rn(v.x, v.y);
        *(__half2*)(&ws[r * 24 + k4 + 2]) = __floats2half2_rn(v.z, v.w);
    }
    __syncthreads();

    float acc[2][4];
#pragma unroll
    for (int nt = 0; nt < 2; nt++)
#pragma unroll
        for (int c = 0; c < 4; c++) acc[nt][c] = 0.0f;

#pragma unroll
    for (int kcl = 0; kcl < 4; kcl++) {
        unsigned a0, a1, a2, a3;
        unsigned aaddr = su32(xs) +
            ((wid * 16 + (lane & 15)) * 72 + kcl * 16 + (lane >> 4) * 8) * 2;
        asm volatile(
            "ldmatrix.sync.aligned.m8n8.x4.shared.b16 {%0,%1,%2,%3}, [%4];"
            : "=r"(a0), "=r"(a1), "=r"(a2), "=r"(a3) : "r"(aaddr));
#pragma unroll
        for (int nt = 0; nt < 2; nt++) {
            unsigned b0, b1;
            unsigned baddr = su32(ws) +
                ((kcl * 16 + (lane & 15)) * 24 + nt * 8) * 2;
            asm volatile(
                "ldmatrix.sync.aligned.m8n8.x2.trans.shared.b16 {%0,%1}, [%2];"
                : "=r"(b0), "=r"(b1) : "r"(baddr));
            asm volatile(
                "mma.sync.aligned.m16n8k16.row.col.f32.f16.f16.f32 "
                "{%0,%1,%2,%3}, {%4,%5,%6,%7}, {%8,%9}, {%0,%1,%2,%3};"
                : "+f"(acc[nt][0]), "+f"(acc[nt][1]),
                  "+f"(acc[nt][2]), "+f"(acc[nt][3])
                : "r"(a0), "r"(a1), "r"(a2), "r"(a3), "r"(b0), "r"(b1));
        }
    }

    int q = lane & 3;
    int r0 = rowBase + wid * 16 + (lane >> 2);
    int r1 = r0 + 8;

#pragma unroll
    for (int nt = 0; nt < 2; nt++) {
        int col = nt * 8 + 2 * q;
        if (r0 < NN)
            *(float2*)(g_g2 + (size_t)r0 * 16 + col) = make_float2(acc[nt][0], acc[nt][1]);
        if (r1 < NN)
            *(float2*)(g_g2 + (size_t)r1 * 16 + col) = make_float2(acc[nt][2], acc[nt][3]);
    }

    float s0 = 0.0f, d0 = 0.0f, s1 = 0.0f, d1 = 0.0f;
#pragma unroll
    for (int nt = 0; nt < 2; nt++) {
        int c0 = nt * 8 + 2 * q, c1 = c0 + 1;
        s0 += acc[nt][0] * sA[c0] + acc[nt][1] * sA[c1];
        d0 += acc[nt][0] * sA[16 + c0] + acc[nt][1] * sA[16 + c1];
        s1 += acc[nt][2] * sA[c0] + acc[nt][3] * sA[c1];
        d1 += acc[nt][2] * sA[16 + c0] + acc[nt][3] * sA[16 + c1];
    }
#pragma unroll
    for (int o = 1; o <= 2; o <<= 1) {
        s0 += __shfl_xor_sync(FULL, s0, o);
        d0 += __shfl_xor_sync(FULL, d0, o);
        s1 += __shfl_xor_sync(FULL, s1, o);
        d1 += __shfl_xor_sync(FULL, d1, o);
    }
    if (q == 0) {
        if (r0 < NN) { g_as2[r0] = s0; g_ad2[r0] = d0; }
        if (r1 < NN) { g_as2[r1] = s1; g_ad2[r1] = d1; }
    }
}

// ---------------- G2: warp-per-dst gather, 4 edges in flight ----------------
__global__ void __launch_bounds__(256) g2_gather(const float* __restrict__ b2,
                                                 float* __restrict__ out) {
    int warp = (blockIdx.x * 256 + threadIdx.x) >> 5;
    int lane = threadIdx.x & 31;
    if (warp >= NN) return;
    int n = warp;
    int off = g_off[n];
    int deg = g_off[n + 1] - off;
    int half = lane >> 4;
    int d16 = lane & 15;
    float ad = g_ad2[n];

    float acc = 0.0f, den = 0.0f;

    int sreg = (lane < deg) ? g_csr[off + lane] : 0;
    float as = g_as2[sreg];

    for (int base = 0; base < deg; base += 32) {
        int sreg_n = 0;
        float as_n = 0.0f;
        if (base + 32 < deg) {
            int nl = base + 32 + lane;
            sreg_n = (nl < deg) ? g_csr[off + nl] : 0;
            as_n = g_as2[sreg_n];
        }

        float e = as + ad;
        e = (e >= 0.0f) ? e : NEG_SLOPE * e;
        float p = __expf(e);
        if (base + lane >= deg) p = 0.0f;
        int cnt = min(32, deg - base);

        int g = 0;
        for (; g + 4 <= cnt; g += 4) {
            int sa = __shfl_sync(FULL, sreg, g + half);
            float pa = __shfl_sync(FULL, p, g + half);
            int sb = __shfl_sync(FULL, sreg, g + 2 + half);
            float pb = __shfl_sync(FULL, p, g + 2 + half);
            float va = g_g2[(size_t)sa * 16 + d16];
            float vb = g_g2[(size_t)sb * 16 + d16];
            acc += pa * va;
            den += pa;
            acc += pb * vb;
            den += pb;
        }
        for (; g < cnt; g += 2) {
            int s = __shfl_sync(FULL, sreg, g + half);
            float pj = __shfl_sync(FULL, p, g + half);
            float v = g_g2[(size_t)s * 16 + d16];
            acc += pj * v;
            den += pj;
        }
        sreg = sreg_n;
        as = as_n;
    }

    acc += __shfl_xor_sync(FULL, acc, 16);
    den += __shfl_xor_sync(FULL, den, 16);

    float z = ((den > 0.0f) ? (acc / den) : 0.0f) + b2[d16];

    float m = z;
#pragma unroll
    for (int ofs = 1; ofs < 16; ofs <<= 1)
        m = fmaxf(m, __shfl_xor_sync(FULL, m, ofs));
    float sum = __expf(z - m);
#pragma unroll
    for (int ofs = 1; ofs < 16; ofs <<= 1)
        sum += __shfl_xor_sync(FULL, sum, ofs);
    float lse = m + logf(sum);

    if (lane < 16) out[(size_t)n * 16 + d16] = z - lse;
}

// ---------------- launcher ----------------
extern "C" void kernel_launch(void* const* d_in, const int* in_sizes, int n_in,
                              void* d_out, int out_size) {
    const float* x   = (const float*)d_in[0];
    const int*   ei  = (const int*)d_in[1];
    const float* W1  = (const float*)d_in[2];
    const float* a1s = (const float*)d_in[3];
    const float* a1d = (const float*)d_in[4];
    const float* b1  = (const float*)d_in[5];
    const float* W2  = (const float*)d_in[6];
    const float* a2s = (const float*)d_in[7];
    const float* a2d = (const float*)d_in[8];
    const float* b2  = (const float*)d_in[9];
    float* out = (float*)d_out;

    const int* src = ei;
    const int* dst = ei + EE;

    const int TB = 256;
    kA_gemm1_hist<<<TC_BLOCKS + HIST_BLOCKS, TB>>>(x, W1, a1s, a1d, dst);
    s1_scan<<<NBLK, SCAN_B>>>();
    s3_apply<<<NBLK, SCAN_B>>>();
    k_scatter<<<(EE / 4 + TB - 1) / TB, TB>>>(src, dst);
    g1_gather<<<(NN * 32 + TB - 1) / TB, TB>>>(b1);
    k5_gemm2<<<TC_BLOCKS, TB>>>(W2, a2s, a2d);
    g2_gather<<<(NN * 32 + TB - 1) / TB, TB>>>(b2, out);
}